// round 13
// baseline (speedup 1.0000x reference)
#include <cuda_runtime.h>
#include <cuda_bf16.h>
#include <cstdint>

// Problem constants: PROJ=128, H=128, G=2, D=96, T=33, NEG=-1e9

#define NEG_VAL (-1000000000.0f)

// Scratch (device globals -- no allocations allowed)
__device__ float g_E[2 * 33 * 96 * 128];   // node embeddings
__device__ float g_A[2 * 32 * 96 * 128];   // xne @ udW1[0:128]
__device__ float g_B[2 * 32 * 96 * 128];   // xce @ udW1[128:256]
__device__ float g_C[2 * 96 * 96 * 128];   // ee  @ udW1[256:288]

// ---- tf32 helpers -----------------------------------------------------------
__device__ __forceinline__ uint32_t tf32r(float x) {
    uint32_t r;
    asm("cvt.rna.tf32.f32 %0, %1;" : "=r"(r) : "f"(x));
    return r;
}
__device__ __forceinline__ float tf32f(float x) {
    return __uint_as_float(tf32r(x));
}
__device__ __forceinline__ void mma_tf32(float c[4], uint32_t a0, uint32_t a1,
                                         uint32_t a2, uint32_t a3,
                                         uint32_t b0, uint32_t b1) {
    asm("mma.sync.aligned.m16n8k8.row.col.f32.tf32.tf32.f32 "
        "{%0,%1,%2,%3},{%4,%5,%6,%7},{%8,%9},{%0,%1,%2,%3};"
        : "+f"(c[0]), "+f"(c[1]), "+f"(c[2]), "+f"(c[3])
        : "r"(a0), "r"(a1), "r"(a2), "r"(a3), "r"(b0), "r"(b1));
}

// ---------------------------------------------------------------------------
// Fused kernel 1+3: node embeddings AND edge MLP + C projection. 256 threads.
//   blocks [0, 198):   E rows 32/block; two 128-thread halves (16 rows each)
//                      share one weight stream (half 2 L1-hits half 1's LDGs).
//   blocks [198, 390): edge MLP + C projection, one (g,i)/block.
// ---------------------------------------------------------------------------
#define EROWS 32
#define NE_BLOCKS 198     // 6336 / 32
__global__ void __launch_bounds__(256) k_fused13(
        const float* __restrict__ x,
        const float* __restrict__ neW1, const float* __restrict__ neb1,
        const float* __restrict__ neW2, const float* __restrict__ neb2,
        const float* __restrict__ edge_w,
        const float* __restrict__ eeW1, const float* __restrict__ eeb1,
        const float* __restrict__ eeW2, const float* __restrict__ eeb2,
        const float* __restrict__ udW1) {
    __shared__ __align__(16) float sm[8500];   // 34 KB union buffer
    int tid = threadIdx.x;  // 256

    if (blockIdx.x < NE_BLOCKS) {
        // ---- node embeddings: 32 rows, two halves of 16 ----
        float (*xv)[129] = reinterpret_cast<float(*)[129]>(sm);            // 32x129
        float (*y1)[128] = reinterpret_cast<float(*)[128]>(sm + 32 * 129); // 32x128

        int r0 = blockIdx.x * EROWS;
        int g = r0 / (33 * 96);
        int rem = r0 % (33 * 96);
        int t = rem / 96;
        int i0 = rem % 96;                 // multiple of 32 -> same (g,t) rows
        const float* xb = x + (size_t)(g * 33 + t) * 128 * 192 + 96 * g + i0;

        // load x: 32 rows x 128 h = 4096; 32 lanes read 32 contiguous ii
#pragma unroll
        for (int it = 0; it < 16; it++) {
            int e = tid + it * 256;
            int h = e >> 5;
            int ii = e & 31;
            xv[ii][h] = xb[h * 192 + ii];
        }
        __syncthreads();

        int col = tid & 127;
        int rh = (tid >> 7) * 16;          // row-half base: 0 or 16

        float acc[16];
#pragma unroll
        for (int r = 0; r < 16; r++) acc[r] = neb1[col];
        for (int k = 0; k < 128; k++) {
            float w = neW1[k * 128 + col];
#pragma unroll
            for (int r = 0; r < 16; r++) acc[r] += xv[rh + r][k] * w;
        }
#pragma unroll
        for (int r = 0; r < 16; r++) y1[rh + r][col] = fmaxf(acc[r], 0.0f);
        __syncthreads();

#pragma unroll
        for (int r = 0; r < 16; r++) acc[r] = neb2[col];
        for (int k = 0; k < 128; k++) {
            float w = neW2[k * 128 + col];
#pragma unroll
            for (int r = 0; r < 16; r++) acc[r] += y1[rh + r][k] * w;
        }
#pragma unroll
        for (int r = 0; r < 16; r++)
            g_E[(size_t)(r0 + rh + r) * 128 + col] = fmaxf(acc[r], 0.0f);
    } else {
        // ---- edge MLP + C projection ----
        int blk = blockIdx.x - NE_BLOCKS;
        int g = blk / 96;
        int i = blk % 96;

        float (*l2s)[33] = reinterpret_cast<float(*)[33]>(sm);  // 96x33
        float* w1s  = sm + 3168;
        float* b1s  = sm + 3200;
        float* b2s  = sm + 3232;
        float* w2s  = sm + 3264;
        float* w1cs = sm + 4288;
        float* ews  = sm + 8384;

        if (tid < 32) { w1s[tid] = eeW1[tid]; b1s[tid] = eeb1[tid]; b2s[tid] = eeb2[tid]; }
        for (int e = tid; e < 1024; e += 256) w2s[e] = eeW2[e];
        for (int e = tid; e < 4096; e += 256) w1cs[e] = udW1[256 * 128 + e];
        if (tid >= 128 && tid < 224) {
            int j = tid - 128;
            ews[j] = edge_w[(96 * g + i) * 192 + 96 * g + j];
        }
        __syncthreads();

        for (int e = tid; e < 96 * 32; e += 256) {
            int j = e >> 5, q = e & 31;
            float e0 = ews[j];
            float a = b2s[q];
#pragma unroll
            for (int p = 0; p < 32; p++) {
                float l1 = fmaxf(e0 * w1s[p] + b1s[p], 0.0f);
                a += l1 * w2s[p * 32 + q];
            }
            l2s[j][q] = fmaxf(a, 0.0f);
        }
        __syncthreads();

        int col = tid & 127;
        int jh = tid >> 7;                 // 0 or 1: even/odd j
        float* Cout = g_C + (size_t)((g * 96 + i) * 96) * 128;
        for (int j = jh; j < 96; j += 2) {
            float a = 0.0f;
#pragma unroll
            for (int q = 0; q < 32; q++) a += l2s[j][q] * w1cs[q * 128 + col];
            Cout[j * 128 + col] = a;
        }
    }
}

// ---------------------------------------------------------------------------
// Kernel 2: A/B projections + dist head. 512 threads = 4 x 128-thread weight
// streams over 32 rows: q0: A=En@udW1[0:128], q1: B=Ec@udW1[128:256],
// q2: D1=Ec@dpW1[0:128], q3: D2=En@dpW1[128:256].
// ---------------------------------------------------------------------------
#define PROWS 32
__global__ void __launch_bounds__(512) k_proj_dist(
        const float* __restrict__ udW1,
        const float* __restrict__ dpW1, const float* __restrict__ dpb1,
        const float* __restrict__ dpW2, const float* __restrict__ dpb2,
        const float* __restrict__ dpW3, const float* __restrict__ dpb3,
        float* __restrict__ dist_out) {
    int r0 = blockIdx.x * PROWS;
    int tid = threadIdx.x;  // 512
    int g = r0 / (32 * 96);
    int rem = r0 % (32 * 96);
    int t = rem / 96;
    int i0 = rem % 96;      // multiple of 32 -> same (g,t) rows

    __shared__ float Ec[PROWS][128];
    __shared__ float En[PROWS][128];
    __shared__ float pd[PROWS][128];   // partial D, then y1d

    for (int e = tid; e < PROWS * 128; e += 512) {
        int r = e >> 7, k = e & 127;
        Ec[r][k] = g_E[((g * 33 + t) * 96 + i0 + r) * 128 + k];
        En[r][k] = g_E[((g * 33 + t + 1) * 96 + i0 + r) * 128 + k];
    }
    __syncthreads();

    int q = tid >> 7;        // stream 0..3
    int col = tid & 127;

    const float* Wp;
    const float (*src)[128];
    if (q == 0)      { Wp = udW1;             src = En; }
    else if (q == 1) { Wp = udW1 + 128 * 128; src = Ec; }
    else if (q == 2) { Wp = dpW1;             src = Ec; }
    else             { Wp = dpW1 + 128 * 128; src = En; }

    float acc[PROWS];
#pragma unroll
    for (int r = 0; r < PROWS; r++) acc[r] = 0.0f;
    for (int k = 0; k < 128; k++) {
        float wv = Wp[k * 128 + col];
#pragma unroll
        for (int r = 0; r < PROWS; r++) acc[r] += src[r][k] * wv;
    }

    if (q == 0) {
#pragma unroll
        for (int r = 0; r < PROWS; r++) g_A[(size_t)(r0 + r) * 128 + col] = acc[r];
    } else if (q == 1) {
#pragma unroll
        for (int r = 0; r < PROWS; r++) g_B[(size_t)(r0 + r) * 128 + col] = acc[r];
    } else if (q == 2) {
#pragma unroll
        for (int r = 0; r < PROWS; r++) pd[r][col] = acc[r];
    }
    __syncthreads();
    if (q == 3) {
        float db1 = dpb1[col];
#pragma unroll
        for (int r = 0; r < PROWS; r++)
            pd[r][col] = fmaxf(acc[r] + pd[r][col] + db1, 0.0f);
    }
    __syncthreads();

    // dist layers 2+3: warp wr owns rows 2wr, 2wr+1; lane handles n, n+32
    int wr = tid >> 5;
    int lane = tid & 31;
#pragma unroll
    for (int rr = 0; rr < 2; rr++) {
        int row = wr * 2 + rr;
        float s = 0.0f;
#pragma unroll
        for (int nn = 0; nn < 2; nn++) {
            int n = lane + nn * 32;
            float a = dpb2[n];
            for (int k = 0; k < 128; k++) a += pd[row][k] * dpW2[k * 64 + n];
            s += fmaxf(a, 0.0f) * dpW3[n];
        }
#pragma unroll
        for (int off = 16; off; off >>= 1) s += __shfl_xor_sync(0xffffffffu, s, off);
        if (lane == 0) dist_out[r0 + row] = s + dpb3[0];
    }
}

// ---------------------------------------------------------------------------
// Kernel 4 (dominant): per (g,t,i) logits via tf32 mma.sync.
// R9/R10 winner: 96 thr = 3 warps; warp w owns rows [32w,32w+32) = 2 m16
// tiles, all 8 n8 tiles; h tile WARP-PRIVATE (no block barriers in mainloop).
// ---------------------------------------------------------------------------
__global__ void __launch_bounds__(96, 4) k_logits(const float* __restrict__ edge_w,
                                                  const float* __restrict__ udb1,
                                                  const float* __restrict__ udW2,
                                                  const float* __restrict__ udb2,
                                                  const float* __restrict__ udW3,
                                                  const float* __restrict__ udb3,
                                                  float* __restrict__ out) {
    int bid = blockIdx.x;                 // g*32*96 + t*96 + i
    int g = bid / (32 * 96);
    int rem = bid % (32 * 96);
    int t = rem / 96;
    int i = rem % 96;
    int tid = threadIdx.x;
    int l = tid & 31;                     // lane
    int w = tid >> 5;                     // warp 0..2
    int tg = l & 3;                       // threadID_in_group
    int gp = l >> 2;                      // groupID 0..7
    int jb = w * 32;                      // warp's 32-row base (2 m16 tiles)

    __shared__ __align__(16) float sW2[128 * 64];   // 32 KB, xor-swizzled rows
    __shared__ __align__(16) float sh[96 * 36];     // h chunk, rows warp-private
    __shared__ __align__(16) float sA[128];
    __shared__ float sW3[64];
    __shared__ float sb2[64];
    __shared__ float ews[96];

    // Stage W2 (tf32-rounded), per-row XOR-8 swizzle: phys n = n ^ (8*(k&3))
    for (int e = tid; e < 2048; e += 96) {
        int k = e >> 4, nq = e & 15;
        float4 v = reinterpret_cast<const float4*>(udW2)[e];
        v.x = tf32f(v.x);
        v.y = tf32f(v.y);
        v.z = tf32f(v.z);
        v.w = tf32f(v.w);
        int n0 = (nq * 4) ^ (8 * (k & 3));
        *reinterpret_cast<float4*>(sW2 + k * 64 + n0) = v;
    }
    for (int e = tid; e < 128; e += 96) sA[e] = g_A[(size_t)bid * 128 + e] + udb1[e];
    if (tid < 64) { sW3[tid] = udW3[tid]; sb2[tid] = udb2[tid]; }
    ews[tid] = edge_w[(size_t)(96 * g + i) * 192 + 96 * g + tid];

    const float* Bb = g_B + (size_t)((g * 32 + t) * 96) * 128;
    const float* Cb = g_C + (size_t)((g * 96 + i) * 96) * 128;

    // Precompute swizzled W2 column per (lane, nt)
    int ncol[8];
#pragma unroll
    for (int nt = 0; nt < 8; nt++) ncol[nt] = (nt * 8 + gp) ^ (8 * tg);

    float acc[2][8][4];
#pragma unroll
    for (int mt = 0; mt < 2; mt++)
#pragma unroll
        for (int nt = 0; nt < 8; nt++)
#pragma unroll
            for (int p = 0; p < 4; p++) acc[mt][nt][p] = 0.0f;

    // h-build mapping (warp-private): lane l, unit u -> local row u*4 + l/8,
    // k-quad q = l&7. 8 lanes cover one 128B row segment (coalesced).
    int rloc = l >> 3;
    int q4 = (l & 7) * 4;

    __syncthreads();   // prologue smem ready (only block barrier)

    for (int kt = 0; kt < 4; kt++) {
        int k0 = kt * 32 + q4;
        // Build this warp's 32 rows x 32 k of h
#pragma unroll
        for (int u = 0; u < 8; u++) {
            int j = jb + u * 4 + rloc;
            float4 b4 = *reinterpret_cast<const float4*>(Bb + j * 128 + k0);
            float4 c4 = *reinterpret_cast<const float4*>(Cb + j * 128 + k0);
            float4 a4 = *reinterpret_cast<const float4*>(sA + k0);
            float4 v;
            v.x = tf32f(fmaxf(a4.x + b4.x + c4.x, 0.0f));
            v.y = tf32f(fmaxf(a4.y + b4.y + c4.y, 0.0f));
            v.z = tf32f(fmaxf(a4.z + b4.z + c4.z, 0.0f));
            v.w = tf32f(fmaxf(a4.w + b4.w + c4.w, 0.0f));
            *reinterpret_cast<float4*>(sh + j * 36 + q4) = v;
        }
        __syncwarp();

#pragma unroll
        for (int k8 = 0; k8 < 4; k8++) {
            int kc = k8 * 8;
            uint32_t a[2][4];
#pragma unroll
            for (int mt = 0; mt < 2; mt++) {
                int base = jb + mt * 16;
                a[mt][0] = __float_as_uint(sh[(base + gp) * 36 + kc + tg]);
                a[mt][1] = __float_as_uint(sh[(base + 8 + gp) * 36 + kc + tg]);
                a[mt][2] = __float_as_uint(sh[(base + gp) * 36 + kc + tg + 4]);
                a[mt][3] = __float_as_uint(sh[(base + 8 + gp) * 36 + kc + tg + 4]);
            }
            const float* w2r0 = sW2 + (kt * 32 + kc + tg) * 64;
            const float* w2r1 = w2r0 + 4 * 64;
#pragma unroll
            for (int nt = 0; nt < 8; nt++) {
                uint32_t b0 = __float_as_uint(w2r0[ncol[nt]]);
                uint32_t b1 = __float_as_uint(w2r1[ncol[nt]]);
                mma_tf32(acc[0][nt], a[0][0], a[0][1], a[0][2], a[0][3], b0, b1);
                mma_tf32(acc[1][nt], a[1][0], a[1][1], a[1][2], a[1][3], b0, b1);
            }
        }
        __syncwarp();   // all lanes done reading before next chunk overwrite
    }

    // Epilogue: relu + W3 dot + lane-group reduce + mask + store
    float b3 = udb3[0];
#pragma unroll
    for (int mt = 0; mt < 2; mt++) {
        float s0 = 0.0f, s1 = 0.0f;
#pragma unroll
        for (int nt = 0; nt < 8; nt++) {
            int n = nt * 8 + tg * 2;
            s0 += fmaxf(acc[mt][nt][0] + sb2[n], 0.0f) * sW3[n]
                + fmaxf(acc[mt][nt][1] + sb2[n + 1], 0.0f) * sW3[n + 1];
            s1 += fmaxf(acc[mt][nt][2] + sb2[n], 0.0f) * sW3[n]
                + fmaxf(acc[mt][nt][3] + sb2[n + 1], 0.0f) * sW3[n + 1];
        }
        s0 += __shfl_xor_sync(0xffffffffu, s0, 1);
        s0 += __shfl_xor_sync(0xffffffffu, s0, 2);
        s1 += __shfl_xor_sync(0xffffffffu, s1, 1);
        s1 += __shfl_xor_sync(0xffffffffu, s1, 2);
        if (tg == 0) {
            int jr = jb + mt * 16 + gp;
            float L0 = s0 + b3;
            float L1 = s1 + b3;
            if (ews[jr] == 0.0f && jr != i) L0 = NEG_VAL;
            if (ews[jr + 8] == 0.0f && (jr + 8) != i) L1 = NEG_VAL;
            out[(size_t)bid * 96 + jr] = L0;
            out[(size_t)bid * 96 + jr + 8] = L1;
        }
    }
}

// ---------------------------------------------------------------------------
// Launch
// ---------------------------------------------------------------------------
extern "C" void kernel_launch(void* const* d_in, const int* in_sizes, int n_in,
                              void* d_out, int out_size) {
    int w0 = n_in - 20;
    const float* x      = (const float*)d_in[0];
    const float* edge_w = (const float*)d_in[1];
    const float* neW1 = (const float*)d_in[w0 + 0];
    const float* neb1 = (const float*)d_in[w0 + 1];
    const float* neW2 = (const float*)d_in[w0 + 2];
    const float* neb2 = (const float*)d_in[w0 + 3];
    const float* eeW1 = (const float*)d_in[w0 + 4];
    const float* eeb1 = (const float*)d_in[w0 + 5];
    const float* eeW2 = (const float*)d_in[w0 + 6];
    const float* eeb2 = (const float*)d_in[w0 + 7];
    const float* udW1 = (const float*)d_in[w0 + 8];
    const float* udb1 = (const float*)d_in[w0 + 9];
    const float* udW2 = (const float*)d_in[w0 + 10];
    const float* udb2 = (const float*)d_in[w0 + 11];
    const float* udW3 = (const float*)d_in[w0 + 12];
    const float* udb3 = (const float*)d_in[w0 + 13];
    const float* dpW1 = (const float*)d_in[w0 + 14];
    const float* dpb1 = (const float*)d_in[w0 + 15];
    const float* dpW2 = (const float*)d_in[w0 + 16];
    const float* dpb2 = (const float*)d_in[w0 + 17];
    const float* dpW3 = (const float*)d_in[w0 + 18];
    const float* dpb3 = (const float*)d_in[w0 + 19];

    float* out = (float*)d_out;
    const int CLASS_N = 2 * 32 * 96 * 96;  // 589824
    float* dist_out = out + CLASS_N;

    // 1+3 fused (independent): node embeddings + edge MLP/C projection
    k_fused13<<<NE_BLOCKS + 2 * 96, 256>>>(x, neW1, neb1, neW2, neb2,
                                           edge_w, eeW1, eeb1, eeW2, eeb2, udW1);
    // 2: A/B projections + dist head (needs g_E)
    k_proj_dist<<<6144 / PROWS, 512>>>(udW1, dpW1, dpb1, dpW2, dpb2, dpW3, dpb3, dist_out);
    // 4: main logits kernel (needs g_A, g_B, g_C)
    k_logits<<<2 * 32 * 96, 96>>>(edge_w, udb1, udW2, udb2, udW3, udb3, out);
}

// round 14
// speedup vs baseline: 1.2702x; 1.2702x over previous
#include <cuda_runtime.h>
#include <cuda_bf16.h>
#include <cstdint>

// Problem constants: PROJ=128, H=128, G=2, D=96, T=33, NEG=-1e9

#define NEG_VAL (-1000000000.0f)

// Scratch (device globals -- no allocations allowed)
__device__ float g_E[2 * 33 * 96 * 128];   // node embeddings
__device__ float g_A[2 * 32 * 96 * 128];   // xne @ udW1[0:128]
__device__ float g_B[2 * 32 * 96 * 128];   // xce @ udW1[128:256]
__device__ float g_C[2 * 96 * 96 * 128];   // ee  @ udW1[256:288]

// ---- tf32 helpers -----------------------------------------------------------
__device__ __forceinline__ uint32_t tf32r(float x) {
    uint32_t r;
    asm("cvt.rna.tf32.f32 %0, %1;" : "=r"(r) : "f"(x));
    return r;
}
__device__ __forceinline__ float tf32f(float x) {
    return __uint_as_float(tf32r(x));
}
__device__ __forceinline__ void mma_tf32(float c[4], uint32_t a0, uint32_t a1,
                                         uint32_t a2, uint32_t a3,
                                         uint32_t b0, uint32_t b1) {
    asm("mma.sync.aligned.m16n8k8.row.col.f32.tf32.tf32.f32 "
        "{%0,%1,%2,%3},{%4,%5,%6,%7},{%8,%9},{%0,%1,%2,%3};"
        : "+f"(c[0]), "+f"(c[1]), "+f"(c[2]), "+f"(c[3])
        : "r"(a0), "r"(a1), "r"(a2), "r"(a3), "r"(b0), "r"(b1));
}

// ---------------------------------------------------------------------------
// Fused kernel 1+3 (R12 config, 128 threads): node embeddings AND
// edge MLP + C projection. Inner GEMM loops vectorized (float4 LDS.128
// broadcast of activations, 4 k per iteration).
// ---------------------------------------------------------------------------
#define EROWS 16
#define NE_BLOCKS 396     // 6336 / 16
__global__ void __launch_bounds__(128) k_fused13(
        const float* __restrict__ x,
        const float* __restrict__ neW1, const float* __restrict__ neb1,
        const float* __restrict__ neW2, const float* __restrict__ neb2,
        const float* __restrict__ edge_w,
        const float* __restrict__ eeW1, const float* __restrict__ eeb1,
        const float* __restrict__ eeW2, const float* __restrict__ eeb2,
        const float* __restrict__ udW1) {
    __shared__ __align__(16) float sm[8500];   // 34 KB union buffer
    int tid = threadIdx.x;  // 128

    if (blockIdx.x < NE_BLOCKS) {
        // ---- node embeddings ----
        float (*xv)[132] = reinterpret_cast<float(*)[132]>(sm);            // 16x132
        float (*y1)[128] = reinterpret_cast<float(*)[128]>(sm + 16 * 132); // 16x128

        int r0 = blockIdx.x * EROWS;
        int g = r0 / (33 * 96);
        int rem = r0 % (33 * 96);
        int t = rem / 96;
        int i0 = rem % 96;
        const float* xb = x + (size_t)(g * 33 + t) * 128 * 192 + 96 * g + i0;

#pragma unroll
        for (int it = 0; it < 16; it++) {
            int e = tid + it * 128;
            int h = e >> 4;
            int ii = e & 15;
            xv[ii][h] = xb[h * 192 + ii];
        }
        __syncthreads();

        float acc[EROWS];
#pragma unroll
        for (int r = 0; r < EROWS; r++) acc[r] = neb1[tid];
        for (int k4 = 0; k4 < 32; k4++) {
            int k = k4 * 4;
            float w0 = neW1[(k + 0) * 128 + tid];
            float w1 = neW1[(k + 1) * 128 + tid];
            float w2 = neW1[(k + 2) * 128 + tid];
            float w3 = neW1[(k + 3) * 128 + tid];
#pragma unroll
            for (int r = 0; r < EROWS; r++) {
                float4 xr = *reinterpret_cast<const float4*>(&xv[r][k]);
                acc[r] += xr.x * w0 + xr.y * w1 + xr.z * w2 + xr.w * w3;
            }
        }
#pragma unroll
        for (int r = 0; r < EROWS; r++) y1[r][tid] = fmaxf(acc[r], 0.0f);
        __syncthreads();

#pragma unroll
        for (int r = 0; r < EROWS; r++) acc[r] = neb2[tid];
        for (int k4 = 0; k4 < 32; k4++) {
            int k = k4 * 4;
            float w0 = neW2[(k + 0) * 128 + tid];
            float w1 = neW2[(k + 1) * 128 + tid];
            float w2 = neW2[(k + 2) * 128 + tid];
            float w3 = neW2[(k + 3) * 128 + tid];
#pragma unroll
            for (int r = 0; r < EROWS; r++) {
                float4 yr = *reinterpret_cast<const float4*>(&y1[r][k]);
                acc[r] += yr.x * w0 + yr.y * w1 + yr.z * w2 + yr.w * w3;
            }
        }
#pragma unroll
        for (int r = 0; r < EROWS; r++) g_E[(r0 + r) * 128 + tid] = fmaxf(acc[r], 0.0f);
    } else {
        // ---- edge MLP + C projection ----
        int blk = blockIdx.x - NE_BLOCKS;
        int g = blk / 96;
        int i = blk % 96;

        float (*l2s)[33] = reinterpret_cast<float(*)[33]>(sm);  // 96x33
        float* w1s  = sm + 3168;
        float* b1s  = sm + 3200;
        float* b2s  = sm + 3232;
        float* w2s  = sm + 3264;
        float* w1cs = sm + 4288;
        float* ews  = sm + 8384;

        if (tid < 32) { w1s[tid] = eeW1[tid]; b1s[tid] = eeb1[tid]; b2s[tid] = eeb2[tid]; }
        for (int e = tid; e < 1024; e += 128) w2s[e] = eeW2[e];
        for (int e = tid; e < 4096; e += 128) w1cs[e] = udW1[256 * 128 + e];
        if (tid < 96) ews[tid] = edge_w[(96 * g + i) * 192 + 96 * g + tid];
        __syncthreads();

        for (int e = tid; e < 96 * 32; e += 128) {
            int j = e >> 5, q = e & 31;
            float e0 = ews[j];
            float a = b2s[q];
#pragma unroll
            for (int p = 0; p < 32; p++) {
                float l1 = fmaxf(e0 * w1s[p] + b1s[p], 0.0f);
                a += l1 * w2s[p * 32 + q];
            }
            l2s[j][q] = fmaxf(a, 0.0f);
        }
        __syncthreads();

        float* Cout = g_C + (size_t)((g * 96 + i) * 96) * 128;
        for (int j = 0; j < 96; j++) {
            float a = 0.0f;
#pragma unroll
            for (int q = 0; q < 32; q++) a += l2s[j][q] * w1cs[q * 128 + tid];
            Cout[j * 128 + tid] = a;
        }
    }
}

// ---------------------------------------------------------------------------
// Kernel 2 (R12 config): A/B projections + dist head. 512 threads = 4 x
// 128-thread weight streams over 16 rows. Inner loops float4-vectorized.
// ---------------------------------------------------------------------------
#define PROWS 16
__global__ void __launch_bounds__(512) k_proj_dist(
        const float* __restrict__ udW1,
        const float* __restrict__ dpW1, const float* __restrict__ dpb1,
        const float* __restrict__ dpW2, const float* __restrict__ dpb2,
        const float* __restrict__ dpW3, const float* __restrict__ dpb3,
        float* __restrict__ dist_out) {
    int r0 = blockIdx.x * PROWS;
    int tid = threadIdx.x;  // 512
    int g = r0 / (32 * 96);
    int rem = r0 % (32 * 96);
    int t = rem / 96;
    int i0 = rem % 96;

    __shared__ __align__(16) float Ec[PROWS][128];
    __shared__ __align__(16) float En[PROWS][128];
    __shared__ __align__(16) float pd[PROWS][128];   // partial D, then y1d

    for (int e = tid; e < PROWS * 128; e += 512) {
        int r = e >> 7, k = e & 127;
        Ec[r][k] = g_E[((g * 33 + t) * 96 + i0 + r) * 128 + k];
        En[r][k] = g_E[((g * 33 + t + 1) * 96 + i0 + r) * 128 + k];
    }
    __syncthreads();

    int q = tid >> 7;        // stream 0..3
    int col = tid & 127;

    const float* Wp;
    const float (*src)[128];
    if (q == 0)      { Wp = udW1;             src = En; }
    else if (q == 1) { Wp = udW1 + 128 * 128; src = Ec; }
    else if (q == 2) { Wp = dpW1;             src = Ec; }
    else             { Wp = dpW1 + 128 * 128; src = En; }

    float acc[PROWS];
#pragma unroll
    for (int r = 0; r < PROWS; r++) acc[r] = 0.0f;
    for (int k4 = 0; k4 < 32; k4++) {
        int k = k4 * 4;
        float w0 = Wp[(k + 0) * 128 + col];
        float w1 = Wp[(k + 1) * 128 + col];
        float w2 = Wp[(k + 2) * 128 + col];
        float w3 = Wp[(k + 3) * 128 + col];
#pragma unroll
        for (int r = 0; r < PROWS; r++) {
            float4 e4 = *reinterpret_cast<const float4*>(&src[r][k]);
            acc[r] += e4.x * w0 + e4.y * w1 + e4.z * w2 + e4.w * w3;
        }
    }

    if (q == 0) {
#pragma unroll
        for (int r = 0; r < PROWS; r++) g_A[(size_t)(r0 + r) * 128 + col] = acc[r];
    } else if (q == 1) {
#pragma unroll
        for (int r = 0; r < PROWS; r++) g_B[(size_t)(r0 + r) * 128 + col] = acc[r];
    } else if (q == 2) {
#pragma unroll
        for (int r = 0; r < PROWS; r++) pd[r][col] = acc[r];
    }
    __syncthreads();
    if (q == 3) {
        float db1 = dpb1[col];
#pragma unroll
        for (int r = 0; r < PROWS; r++)
            pd[r][col] = fmaxf(acc[r] + pd[r][col] + db1, 0.0f);
    }
    __syncthreads();

    // dist layers 2+3: warp wr owns row wr; lane handles n = lane, lane+32
    int wr = tid >> 5;
    int lane = tid & 31;
    float s = 0.0f;
#pragma unroll
    for (int nn = 0; nn < 2; nn++) {
        int n = lane + nn * 32;
        float a = dpb2[n];
        for (int k4 = 0; k4 < 32; k4++) {
            int k = k4 * 4;
            float4 p4 = *reinterpret_cast<const float4*>(&pd[wr][k]);
            a += p4.x * dpW2[(k + 0) * 64 + n] + p4.y * dpW2[(k + 1) * 64 + n]
               + p4.z * dpW2[(k + 2) * 64 + n] + p4.w * dpW2[(k + 3) * 64 + n];
        }
        s += fmaxf(a, 0.0f) * dpW3[n];
    }
#pragma unroll
    for (int off = 16; off; off >>= 1) s += __shfl_xor_sync(0xffffffffu, s, off);
    if (lane == 0) dist_out[r0 + wr] = s + dpb3[0];
}

// ---------------------------------------------------------------------------
// Kernel 4 (dominant, unchanged R12): per (g,t,i) logits via tf32 mma.sync.
// 96 thr = 3 warps; warp w owns rows [32w,32w+32) = 2 m16 tiles, all 8 n8
// tiles; h tile WARP-PRIVATE (no block barriers in mainloop).
// ---------------------------------------------------------------------------
__global__ void __launch_bounds__(96, 4) k_logits(const float* __restrict__ edge_w,
                                                  const float* __restrict__ udb1,
                                                  const float* __restrict__ udW2,
                                                  const float* __restrict__ udb2,
                                                  const float* __restrict__ udW3,
                                                  const float* __restrict__ udb3,
                                                  float* __restrict__ out) {
    int bid = blockIdx.x;                 // g*32*96 + t*96 + i
    int g = bid / (32 * 96);
    int rem = bid % (32 * 96);
    int t = rem / 96;
    int i = rem % 96;
    int tid = threadIdx.x;
    int l = tid & 31;                     // lane
    int w = tid >> 5;                     // warp 0..2
    int tg = l & 3;                       // threadID_in_group
    int gp = l >> 2;                      // groupID 0..7
    int jb = w * 32;                      // warp's 32-row base (2 m16 tiles)

    __shared__ __align__(16) float sW2[128 * 64];   // 32 KB, xor-swizzled rows
    __shared__ __align__(16) float sh[96 * 36];     // h chunk, rows warp-private
    __shared__ __align__(16) float sA[128];
    __shared__ float sW3[64];
    __shared__ float sb2[64];
    __shared__ float ews[96];

    // Stage W2 (tf32-rounded), per-row XOR-8 swizzle: phys n = n ^ (8*(k&3))
    for (int e = tid; e < 2048; e += 96) {
        int k = e >> 4, nq = e & 15;
        float4 v = reinterpret_cast<const float4*>(udW2)[e];
        v.x = tf32f(v.x);
        v.y = tf32f(v.y);
        v.z = tf32f(v.z);
        v.w = tf32f(v.w);
        int n0 = (nq * 4) ^ (8 * (k & 3));
        *reinterpret_cast<float4*>(sW2 + k * 64 + n0) = v;
    }
    for (int e = tid; e < 128; e += 96) sA[e] = g_A[(size_t)bid * 128 + e] + udb1[e];
    if (tid < 64) { sW3[tid] = udW3[tid]; sb2[tid] = udb2[tid]; }
    ews[tid] = edge_w[(size_t)(96 * g + i) * 192 + 96 * g + tid];

    const float* Bb = g_B + (size_t)((g * 32 + t) * 96) * 128;
    const float* Cb = g_C + (size_t)((g * 96 + i) * 96) * 128;

    // Precompute swizzled W2 column per (lane, nt)
    int ncol[8];
#pragma unroll
    for (int nt = 0; nt < 8; nt++) ncol[nt] = (nt * 8 + gp) ^ (8 * tg);

    float acc[2][8][4];
#pragma unroll
    for (int mt = 0; mt < 2; mt++)
#pragma unroll
        for (int nt = 0; nt < 8; nt++)
#pragma unroll
            for (int p = 0; p < 4; p++) acc[mt][nt][p] = 0.0f;

    // h-build mapping (warp-private): lane l, unit u -> local row u*4 + l/8,
    // k-quad q = l&7. 8 lanes cover one 128B row segment (coalesced).
    int rloc = l >> 3;
    int q4 = (l & 7) * 4;

    __syncthreads();   // prologue smem ready (only block barrier)

    for (int kt = 0; kt < 4; kt++) {
        int k0 = kt * 32 + q4;
        // Build this warp's 32 rows x 32 k of h
#pragma unroll
        for (int u = 0; u < 8; u++) {
            int j = jb + u * 4 + rloc;
            float4 b4 = *reinterpret_cast<const float4*>(Bb + j * 128 + k0);
            float4 c4 = *reinterpret_cast<const float4*>(Cb + j * 128 + k0);
            float4 a4 = *reinterpret_cast<const float4*>(sA + k0);
            float4 v;
            v.x = tf32f(fmaxf(a4.x + b4.x + c4.x, 0.0f));
            v.y = tf32f(fmaxf(a4.y + b4.y + c4.y, 0.0f));
            v.z = tf32f(fmaxf(a4.z + b4.z + c4.z, 0.0f));
            v.w = tf32f(fmaxf(a4.w + b4.w + c4.w, 0.0f));
            *reinterpret_cast<float4*>(sh + j * 36 + q4) = v;
        }
        __syncwarp();

#pragma unroll
        for (int k8 = 0; k8 < 4; k8++) {
            int kc = k8 * 8;
            uint32_t a[2][4];
#pragma unroll
            for (int mt = 0; mt < 2; mt++) {
                int base = jb + mt * 16;
                a[mt][0] = __float_as_uint(sh[(base + gp) * 36 + kc + tg]);
                a[mt][1] = __float_as_uint(sh[(base + 8 + gp) * 36 + kc + tg]);
                a[mt][2] = __float_as_uint(sh[(base + gp) * 36 + kc + tg + 4]);
                a[mt][3] = __float_as_uint(sh[(base + 8 + gp) * 36 + kc + tg + 4]);
            }
            const float* w2r0 = sW2 + (kt * 32 + kc + tg) * 64;
            const float* w2r1 = w2r0 + 4 * 64;
#pragma unroll
            for (int nt = 0; nt < 8; nt++) {
                uint32_t b0 = __float_as_uint(w2r0[ncol[nt]]);
                uint32_t b1 = __float_as_uint(w2r1[ncol[nt]]);
                mma_tf32(acc[0][nt], a[0][0], a[0][1], a[0][2], a[0][3], b0, b1);
                mma_tf32(acc[1][nt], a[1][0], a[1][1], a[1][2], a[1][3], b0, b1);
            }
        }
        __syncwarp();   // all lanes done reading before next chunk overwrite
    }

    // Epilogue: relu + W3 dot + lane-group reduce + mask + store
    float b3 = udb3[0];
#pragma unroll
    for (int mt = 0; mt < 2; mt++) {
        float s0 = 0.0f, s1 = 0.0f;
#pragma unroll
        for (int nt = 0; nt < 8; nt++) {
            int n = nt * 8 + tg * 2;
            s0 += fmaxf(acc[mt][nt][0] + sb2[n], 0.0f) * sW3[n]
                + fmaxf(acc[mt][nt][1] + sb2[n + 1], 0.0f) * sW3[n + 1];
            s1 += fmaxf(acc[mt][nt][2] + sb2[n], 0.0f) * sW3[n]
                + fmaxf(acc[mt][nt][3] + sb2[n + 1], 0.0f) * sW3[n + 1];
        }
        s0 += __shfl_xor_sync(0xffffffffu, s0, 1);
        s0 += __shfl_xor_sync(0xffffffffu, s0, 2);
        s1 += __shfl_xor_sync(0xffffffffu, s1, 1);
        s1 += __shfl_xor_sync(0xffffffffu, s1, 2);
        if (tg == 0) {
            int jr = jb + mt * 16 + gp;
            float L0 = s0 + b3;
            float L1 = s1 + b3;
            if (ews[jr] == 0.0f && jr != i) L0 = NEG_VAL;
            if (ews[jr + 8] == 0.0f && (jr + 8) != i) L1 = NEG_VAL;
            out[(size_t)bid * 96 + jr] = L0;
            out[(size_t)bid * 96 + jr + 8] = L1;
        }
    }
}

// ---------------------------------------------------------------------------
// Launch
// ---------------------------------------------------------------------------
extern "C" void kernel_launch(void* const* d_in, const int* in_sizes, int n_in,
                              void* d_out, int out_size) {
    int w0 = n_in - 20;
    const float* x      = (const float*)d_in[0];
    const float* edge_w = (const float*)d_in[1];
    const float* neW1 = (const float*)d_in[w0 + 0];
    const float* neb1 = (const float*)d_in[w0 + 1];
    const float* neW2 = (const float*)d_in[w0 + 2];
    const float* neb2 = (const float*)d_in[w0 + 3];
    const float* eeW1 = (const float*)d_in[w0 + 4];
    const float* eeb1 = (const float*)d_in[w0 + 5];
    const float* eeW2 = (const float*)d_in[w0 + 6];
    const float* eeb2 = (const float*)d_in[w0 + 7];
    const float* udW1 = (const float*)d_in[w0 + 8];
    const float* udb1 = (const float*)d_in[w0 + 9];
    const float* udW2 = (const float*)d_in[w0 + 10];
    const float* udb2 = (const float*)d_in[w0 + 11];
    const float* udW3 = (const float*)d_in[w0 + 12];
    const float* udb3 = (const float*)d_in[w0 + 13];
    const float* dpW1 = (const float*)d_in[w0 + 14];
    const float* dpb1 = (const float*)d_in[w0 + 15];
    const float* dpW2 = (const float*)d_in[w0 + 16];
    const float* dpb2 = (const float*)d_in[w0 + 17];
    const float* dpW3 = (const float*)d_in[w0 + 18];
    const float* dpb3 = (const float*)d_in[w0 + 19];

    float* out = (float*)d_out;
    const int CLASS_N = 2 * 32 * 96 * 96;  // 589824
    float* dist_out = out + CLASS_N;

    // 1+3 fused (independent): node embeddings + edge MLP/C projection
    k_fused13<<<NE_BLOCKS + 2 * 96, 128>>>(x, neW1, neb1, neW2, neb2,
                                           edge_w, eeW1, eeb1, eeW2, eeb2, udW1);
    // 2: A/B projections + dist head (needs g_E)
    k_proj_dist<<<6144 / PROWS, 512>>>(udW1, dpW1, dpb1, dpW2, dpb2, dpW3, dpb3, dist_out);
    // 4: main logits kernel (needs g_A, g_B, g_C)
    k_logits<<<2 * 32 * 96, 96>>>(edge_w, udb1, udW2, udb2, udW3, udb3, out);
}

// round 15
// speedup vs baseline: 1.2899x; 1.0155x over previous
#include <cuda_runtime.h>
#include <cuda_bf16.h>
#include <cstdint>

// Problem constants: PROJ=128, H=128, G=2, D=96, T=33, NEG=-1e9

#define NEG_VAL (-1000000000.0f)

// Scratch (device globals -- no allocations allowed)
__device__ float g_E[2 * 33 * 96 * 128];   // node embeddings
__device__ float g_A[2 * 32 * 96 * 128];   // xne @ udW1[0:128]
__device__ float g_B[2 * 32 * 96 * 128];   // xce @ udW1[128:256]
__device__ float g_C[2 * 96 * 96 * 128];   // ee  @ udW1[256:288]

// ---- tf32 helpers -----------------------------------------------------------
__device__ __forceinline__ uint32_t tf32r(float x) {
    uint32_t r;
    asm("cvt.rna.tf32.f32 %0, %1;" : "=r"(r) : "f"(x));
    return r;
}
__device__ __forceinline__ float tf32f(float x) {
    return __uint_as_float(tf32r(x));
}
__device__ __forceinline__ void mma_tf32(float c[4], uint32_t a0, uint32_t a1,
                                         uint32_t a2, uint32_t a3,
                                         uint32_t b0, uint32_t b1) {
    asm("mma.sync.aligned.m16n8k8.row.col.f32.tf32.tf32.f32 "
        "{%0,%1,%2,%3},{%4,%5,%6,%7},{%8,%9},{%0,%1,%2,%3};"
        : "+f"(c[0]), "+f"(c[1]), "+f"(c[2]), "+f"(c[3])
        : "r"(a0), "r"(a1), "r"(a2), "r"(a3), "r"(b0), "r"(b1));
}

// ---------------------------------------------------------------------------
// Fused kernel 1+3 (R14, unchanged): node embeddings AND edge MLP + C proj.
// ---------------------------------------------------------------------------
#define EROWS 16
#define NE_BLOCKS 396     // 6336 / 16
__global__ void __launch_bounds__(128) k_fused13(
        const float* __restrict__ x,
        const float* __restrict__ neW1, const float* __restrict__ neb1,
        const float* __restrict__ neW2, const float* __restrict__ neb2,
        const float* __restrict__ edge_w,
        const float* __restrict__ eeW1, const float* __restrict__ eeb1,
        const float* __restrict__ eeW2, const float* __restrict__ eeb2,
        const float* __restrict__ udW1) {
    __shared__ __align__(16) float sm[8500];   // 34 KB union buffer
    int tid = threadIdx.x;  // 128

    if (blockIdx.x < NE_BLOCKS) {
        // ---- node embeddings ----
        float (*xv)[132] = reinterpret_cast<float(*)[132]>(sm);            // 16x132
        float (*y1)[128] = reinterpret_cast<float(*)[128]>(sm + 16 * 132); // 16x128

        int r0 = blockIdx.x * EROWS;
        int g = r0 / (33 * 96);
        int rem = r0 % (33 * 96);
        int t = rem / 96;
        int i0 = rem % 96;
        const float* xb = x + (size_t)(g * 33 + t) * 128 * 192 + 96 * g + i0;

#pragma unroll
        for (int it = 0; it < 16; it++) {
            int e = tid + it * 128;
            int h = e >> 4;
            int ii = e & 15;
            xv[ii][h] = xb[h * 192 + ii];
        }
        __syncthreads();

        float acc[EROWS];
#pragma unroll
        for (int r = 0; r < EROWS; r++) acc[r] = neb1[tid];
        for (int k4 = 0; k4 < 32; k4++) {
            int k = k4 * 4;
            float w0 = neW1[(k + 0) * 128 + tid];
            float w1 = neW1[(k + 1) * 128 + tid];
            float w2 = neW1[(k + 2) * 128 + tid];
            float w3 = neW1[(k + 3) * 128 + tid];
#pragma unroll
            for (int r = 0; r < EROWS; r++) {
                float4 xr = *reinterpret_cast<const float4*>(&xv[r][k]);
                acc[r] += xr.x * w0 + xr.y * w1 + xr.z * w2 + xr.w * w3;
            }
        }
#pragma unroll
        for (int r = 0; r < EROWS; r++) y1[r][tid] = fmaxf(acc[r], 0.0f);
        __syncthreads();

#pragma unroll
        for (int r = 0; r < EROWS; r++) acc[r] = neb2[tid];
        for (int k4 = 0; k4 < 32; k4++) {
            int k = k4 * 4;
            float w0 = neW2[(k + 0) * 128 + tid];
            float w1 = neW2[(k + 1) * 128 + tid];
            float w2 = neW2[(k + 2) * 128 + tid];
            float w3 = neW2[(k + 3) * 128 + tid];
#pragma unroll
            for (int r = 0; r < EROWS; r++) {
                float4 yr = *reinterpret_cast<const float4*>(&y1[r][k]);
                acc[r] += yr.x * w0 + yr.y * w1 + yr.z * w2 + yr.w * w3;
            }
        }
#pragma unroll
        for (int r = 0; r < EROWS; r++) g_E[(r0 + r) * 128 + tid] = fmaxf(acc[r], 0.0f);
    } else {
        // ---- edge MLP + C projection ----
        int blk = blockIdx.x - NE_BLOCKS;
        int g = blk / 96;
        int i = blk % 96;

        float (*l2s)[33] = reinterpret_cast<float(*)[33]>(sm);  // 96x33
        float* w1s  = sm + 3168;
        float* b1s  = sm + 3200;
        float* b2s  = sm + 3232;
        float* w2s  = sm + 3264;
        float* w1cs = sm + 4288;
        float* ews  = sm + 8384;

        if (tid < 32) { w1s[tid] = eeW1[tid]; b1s[tid] = eeb1[tid]; b2s[tid] = eeb2[tid]; }
        for (int e = tid; e < 1024; e += 128) w2s[e] = eeW2[e];
        for (int e = tid; e < 4096; e += 128) w1cs[e] = udW1[256 * 128 + e];
        if (tid < 96) ews[tid] = edge_w[(96 * g + i) * 192 + 96 * g + tid];
        __syncthreads();

        for (int e = tid; e < 96 * 32; e += 128) {
            int j = e >> 5, q = e & 31;
            float e0 = ews[j];
            float a = b2s[q];
#pragma unroll
            for (int p = 0; p < 32; p++) {
                float l1 = fmaxf(e0 * w1s[p] + b1s[p], 0.0f);
                a += l1 * w2s[p * 32 + q];
            }
            l2s[j][q] = fmaxf(a, 0.0f);
        }
        __syncthreads();

        float* Cout = g_C + (size_t)((g * 96 + i) * 96) * 128;
        for (int j = 0; j < 96; j++) {
            float a = 0.0f;
#pragma unroll
            for (int q = 0; q < 32; q++) a += l2s[j][q] * w1cs[q * 128 + tid];
            Cout[j * 128 + tid] = a;
        }
    }
}

// ---------------------------------------------------------------------------
// Kernel 2 (R14, unchanged): A/B projections + dist head. 512 threads = 4 x
// 128-thread weight streams over 16 rows. Inner loops float4-vectorized.
// ---------------------------------------------------------------------------
#define PROWS 16
__global__ void __launch_bounds__(512) k_proj_dist(
        const float* __restrict__ udW1,
        const float* __restrict__ dpW1, const float* __restrict__ dpb1,
        const float* __restrict__ dpW2, const float* __restrict__ dpb2,
        const float* __restrict__ dpW3, const float* __restrict__ dpb3,
        float* __restrict__ dist_out) {
    int r0 = blockIdx.x * PROWS;
    int tid = threadIdx.x;  // 512
    int g = r0 / (32 * 96);
    int rem = r0 % (32 * 96);
    int t = rem / 96;
    int i0 = rem % 96;

    __shared__ __align__(16) float Ec[PROWS][128];
    __shared__ __align__(16) float En[PROWS][128];
    __shared__ __align__(16) float pd[PROWS][128];   // partial D, then y1d

    for (int e = tid; e < PROWS * 128; e += 512) {
        int r = e >> 7, k = e & 127;
        Ec[r][k] = g_E[((g * 33 + t) * 96 + i0 + r) * 128 + k];
        En[r][k] = g_E[((g * 33 + t + 1) * 96 + i0 + r) * 128 + k];
    }
    __syncthreads();

    int q = tid >> 7;        // stream 0..3
    int col = tid & 127;

    const float* Wp;
    const float (*src)[128];
    if (q == 0)      { Wp = udW1;             src = En; }
    else if (q == 1) { Wp = udW1 + 128 * 128; src = Ec; }
    else if (q == 2) { Wp = dpW1;             src = Ec; }
    else             { Wp = dpW1 + 128 * 128; src = En; }

    float acc[PROWS];
#pragma unroll
    for (int r = 0; r < PROWS; r++) acc[r] = 0.0f;
    for (int k4 = 0; k4 < 32; k4++) {
        int k = k4 * 4;
        float w0 = Wp[(k + 0) * 128 + col];
        float w1 = Wp[(k + 1) * 128 + col];
        float w2 = Wp[(k + 2) * 128 + col];
        float w3 = Wp[(k + 3) * 128 + col];
#pragma unroll
        for (int r = 0; r < PROWS; r++) {
            float4 e4 = *reinterpret_cast<const float4*>(&src[r][k]);
            acc[r] += e4.x * w0 + e4.y * w1 + e4.z * w2 + e4.w * w3;
        }
    }

    if (q == 0) {
#pragma unroll
        for (int r = 0; r < PROWS; r++) g_A[(size_t)(r0 + r) * 128 + col] = acc[r];
    } else if (q == 1) {
#pragma unroll
        for (int r = 0; r < PROWS; r++) g_B[(size_t)(r0 + r) * 128 + col] = acc[r];
    } else if (q == 2) {
#pragma unroll
        for (int r = 0; r < PROWS; r++) pd[r][col] = acc[r];
    }
    __syncthreads();
    if (q == 3) {
        float db1 = dpb1[col];
#pragma unroll
        for (int r = 0; r < PROWS; r++)
            pd[r][col] = fmaxf(acc[r] + pd[r][col] + db1, 0.0f);
    }
    __syncthreads();

    // dist layers 2+3: warp wr owns row wr; lane handles n = lane, lane+32
    int wr = tid >> 5;
    int lane = tid & 31;
    float s = 0.0f;
#pragma unroll
    for (int nn = 0; nn < 2; nn++) {
        int n = lane + nn * 32;
        float a = dpb2[n];
        for (int k4 = 0; k4 < 32; k4++) {
            int k = k4 * 4;
            float4 p4 = *reinterpret_cast<const float4*>(&pd[wr][k]);
            a += p4.x * dpW2[(k + 0) * 64 + n] + p4.y * dpW2[(k + 1) * 64 + n]
               + p4.z * dpW2[(k + 2) * 64 + n] + p4.w * dpW2[(k + 3) * 64 + n];
        }
        s += fmaxf(a, 0.0f) * dpW3[n];
    }
#pragma unroll
    for (int off = 16; off; off >>= 1) s += __shfl_xor_sync(0xffffffffu, s, off);
    if (lane == 0) dist_out[r0 + wr] = s + dpb3[0];
}

// ---------------------------------------------------------------------------
// Kernel 4 (dominant): per (g, t-pair, i) logits via tf32 mma.sync.
// R9 warp-private structure (96 thr = 3 warps; warp w owns rows [32w,32w+32)
// = 2 m16 tiles, all 8 n8 tiles; NO block barriers in mainloop), t-PAIRED:
// each block processes t = 2*tp and 2*tp+1, reusing the staged W2 (32 KB)
// and the (g,i)-invariant C rows / ews. Zero extra registers, zero barriers.
// ---------------------------------------------------------------------------
#define TPAIR 2
__global__ void __launch_bounds__(96, 4) k_logits(const float* __restrict__ edge_w,
                                                  const float* __restrict__ udb1,
                                                  const float* __restrict__ udW2,
                                                  const float* __restrict__ udb2,
                                                  const float* __restrict__ udW3,
                                                  const float* __restrict__ udb3,
                                                  float* __restrict__ out) {
    int bid = blockIdx.x;                 // g*16*96 + tp*96 + i
    int g = bid / (16 * 96);
    int rem = bid % (16 * 96);
    int tp = rem / 96;
    int i = rem % 96;
    int tid = threadIdx.x;
    int l = tid & 31;                     // lane
    int w = tid >> 5;                     // warp 0..2
    int tg = l & 3;                       // threadID_in_group
    int gp = l >> 2;                      // groupID 0..7
    int jb = w * 32;                      // warp's 32-row base (2 m16 tiles)

    __shared__ __align__(16) float sW2[128 * 64];   // 32 KB, xor-swizzled rows
    __shared__ __align__(16) float sh[96 * 36];     // h chunk, rows warp-private
    __shared__ __align__(16) float sA[TPAIR * 128];
    __shared__ float sW3[64];
    __shared__ float sb2[64];
    __shared__ float ews[96];

    // Stage W2 (tf32-rounded), per-row XOR-8 swizzle: phys n = n ^ (8*(k&3))
    for (int e = tid; e < 2048; e += 96) {
        int k = e >> 4, nq = e & 15;
        float4 v = reinterpret_cast<const float4*>(udW2)[e];
        v.x = tf32f(v.x);
        v.y = tf32f(v.y);
        v.z = tf32f(v.z);
        v.w = tf32f(v.w);
        int n0 = (nq * 4) ^ (8 * (k & 3));
        *reinterpret_cast<float4*>(sW2 + k * 64 + n0) = v;
    }
    for (int e = tid; e < TPAIR * 128; e += 96) {
        int tt = e >> 7, k = e & 127;
        size_t arow = (size_t)((g * 32 + tp * TPAIR + tt) * 96 + i);
        sA[e] = g_A[arow * 128 + k] + udb1[k];
    }
    if (tid < 64) { sW3[tid] = udW3[tid]; sb2[tid] = udb2[tid]; }
    ews[tid] = edge_w[(size_t)(96 * g + i) * 192 + 96 * g + tid];

    const float* Cb = g_C + (size_t)((g * 96 + i) * 96) * 128;

    // Precompute swizzled W2 column per (lane, nt)
    int ncol[8];
#pragma unroll
    for (int nt = 0; nt < 8; nt++) ncol[nt] = (nt * 8 + gp) ^ (8 * tg);

    // h-build mapping (warp-private): lane l, unit u -> local row u*4 + l/8,
    // k-quad q = l&7. 8 lanes cover one 128B row segment (coalesced).
    int rloc = l >> 3;
    int q4 = (l & 7) * 4;

    float b3 = udb3[0];

    __syncthreads();   // prologue smem ready (only block barrier)

    for (int tt = 0; tt < TPAIR; tt++) {
        int t = tp * TPAIR + tt;
        const float* Bb = g_B + (size_t)((g * 32 + t) * 96) * 128;
        const float* sAt = sA + tt * 128;

        float acc[2][8][4];
#pragma unroll
        for (int mt = 0; mt < 2; mt++)
#pragma unroll
            for (int nt = 0; nt < 8; nt++)
#pragma unroll
                for (int p = 0; p < 4; p++) acc[mt][nt][p] = 0.0f;

        for (int kt = 0; kt < 4; kt++) {
            int k0 = kt * 32 + q4;
            // Build this warp's 32 rows x 32 k of h
#pragma unroll
            for (int u = 0; u < 8; u++) {
                int j = jb + u * 4 + rloc;
                float4 b4 = *reinterpret_cast<const float4*>(Bb + j * 128 + k0);
                float4 c4 = *reinterpret_cast<const float4*>(Cb + j * 128 + k0);
                float4 a4 = *reinterpret_cast<const float4*>(sAt + k0);
                float4 v;
                v.x = tf32f(fmaxf(a4.x + b4.x + c4.x, 0.0f));
                v.y = tf32f(fmaxf(a4.y + b4.y + c4.y, 0.0f));
                v.z = tf32f(fmaxf(a4.z + b4.z + c4.z, 0.0f));
                v.w = tf32f(fmaxf(a4.w + b4.w + c4.w, 0.0f));
                *reinterpret_cast<float4*>(sh + j * 36 + q4) = v;
            }
            __syncwarp();

#pragma unroll
            for (int k8 = 0; k8 < 4; k8++) {
                int kc = k8 * 8;
                uint32_t a[2][4];
#pragma unroll
                for (int mt = 0; mt < 2; mt++) {
                    int base = jb + mt * 16;
                    a[mt][0] = __float_as_uint(sh[(base + gp) * 36 + kc + tg]);
                    a[mt][1] = __float_as_uint(sh[(base + 8 + gp) * 36 + kc + tg]);
                    a[mt][2] = __float_as_uint(sh[(base + gp) * 36 + kc + tg + 4]);
                    a[mt][3] = __float_as_uint(sh[(base + 8 + gp) * 36 + kc + tg + 4]);
                }
                const float* w2r0 = sW2 + (kt * 32 + kc + tg) * 64;
                const float* w2r1 = w2r0 + 4 * 64;
#pragma unroll
                for (int nt = 0; nt < 8; nt++) {
                    uint32_t b0 = __float_as_uint(w2r0[ncol[nt]]);
                    uint32_t b1 = __float_as_uint(w2r1[ncol[nt]]);
                    mma_tf32(acc[0][nt], a[0][0], a[0][1], a[0][2], a[0][3], b0, b1);
                    mma_tf32(acc[1][nt], a[1][0], a[1][1], a[1][2], a[1][3], b0, b1);
                }
            }
            __syncwarp();   // all lanes done reading before next chunk overwrite
        }

        // Epilogue for this t: relu + W3 dot + lane-group reduce + mask + store
#pragma unroll
        for (int mt = 0; mt < 2; mt++) {
            float s0 = 0.0f, s1 = 0.0f;
#pragma unroll
            for (int nt = 0; nt < 8; nt++) {
                int n = nt * 8 + tg * 2;
                s0 += fmaxf(acc[mt][nt][0] + sb2[n], 0.0f) * sW3[n]
                    + fmaxf(acc[mt][nt][1] + sb2[n + 1], 0.0f) * sW3[n + 1];
                s1 += fmaxf(acc[mt][nt][2] + sb2[n], 0.0f) * sW3[n]
                    + fmaxf(acc[mt][nt][3] + sb2[n + 1], 0.0f) * sW3[n + 1];
            }
            s0 += __shfl_xor_sync(0xffffffffu, s0, 1);
            s0 += __shfl_xor_sync(0xffffffffu, s0, 2);
            s1 += __shfl_xor_sync(0xffffffffu, s1, 1);
            s1 += __shfl_xor_sync(0xffffffffu, s1, 2);
            if (tg == 0) {
                int jr = jb + mt * 16 + gp;
                float L0 = s0 + b3;
                float L1 = s1 + b3;
                if (ews[jr] == 0.0f && jr != i) L0 = NEG_VAL;
                if (ews[jr + 8] == 0.0f && (jr + 8) != i) L1 = NEG_VAL;
                size_t orow = (size_t)((g * 32 + t) * 96 + i) * 96;
                out[orow + jr] = L0;
                out[orow + jr + 8] = L1;
            }
        }
    }
}

// ---------------------------------------------------------------------------
// Launch
// ---------------------------------------------------------------------------
extern "C" void kernel_launch(void* const* d_in, const int* in_sizes, int n_in,
                              void* d_out, int out_size) {
    int w0 = n_in - 20;
    const float* x      = (const float*)d_in[0];
    const float* edge_w = (const float*)d_in[1];
    const float* neW1 = (const float*)d_in[w0 + 0];
    const float* neb1 = (const float*)d_in[w0 + 1];
    const float* neW2 = (const float*)d_in[w0 + 2];
    const float* neb2 = (const float*)d_in[w0 + 3];
    const float* eeW1 = (const float*)d_in[w0 + 4];
    const float* eeb1 = (const float*)d_in[w0 + 5];
    const float* eeW2 = (const float*)d_in[w0 + 6];
    const float* eeb2 = (const float*)d_in[w0 + 7];
    const float* udW1 = (const float*)d_in[w0 + 8];
    const float* udb1 = (const float*)d_in[w0 + 9];
    const float* udW2 = (const float*)d_in[w0 + 10];
    const float* udb2 = (const float*)d_in[w0 + 11];
    const float* udW3 = (const float*)d_in[w0 + 12];
    const float* udb3 = (const float*)d_in[w0 + 13];
    const float* dpW1 = (const float*)d_in[w0 + 14];
    const float* dpb1 = (const float*)d_in[w0 + 15];
    const float* dpW2 = (const float*)d_in[w0 + 16];
    const float* dpb2 = (const float*)d_in[w0 + 17];
    const float* dpW3 = (const float*)d_in[w0 + 18];
    const float* dpb3 = (const float*)d_in[w0 + 19];

    float* out = (float*)d_out;
    const int CLASS_N = 2 * 32 * 96 * 96;  // 589824
    float* dist_out = out + CLASS_N;

    // 1+3 fused (independent): node embeddings + edge MLP/C projection
    k_fused13<<<NE_BLOCKS + 2 * 96, 128>>>(x, neW1, neb1, neW2, neb2,
                                           edge_w, eeW1, eeb1, eeW2, eeb2, udW1);
    // 2: A/B projections + dist head (needs g_E)
    k_proj_dist<<<6144 / PROWS, 512>>>(udW1, dpW1, dpb1, dpW2, dpb2, dpW3, dpb3, dist_out);
    // 4: main logits kernel (needs g_A, g_B, g_C), t-paired
    k_logits<<<2 * 16 * 96, 96>>>(edge_w, udb1, udW2, udb2, udW3, udb3, out);
}